// round 6
// baseline (speedup 1.0000x reference)
#include <cuda_runtime.h>
#include <stdint.h>

#define DIM   64
#define MAX_N 150016           // 100000 users + 50000 items, padded
#define MAX_E 1300000          // actual E = 1,200,000 (incl. flipped copy)

#define SCAN_TB    256
#define SCAN_ITEMS 8           // 2048 elements per block
#define SCAN_CHUNK (SCAN_TB * SCAN_ITEMS)
#define MAX_SCAN_BLOCKS 512

// ---------------------------------------------------------------------------
// Scratch: __device__ globals only (no allocations allowed anywhere).
// ---------------------------------------------------------------------------
__device__ float  g_bufA[MAX_N * DIM];   // ping (w0, then w2)
__device__ float  g_bufB[MAX_N * DIM];   // pong (w1)
__device__ float4 g_dinvs[MAX_N];        // (dinv, dinv^2, sqrt(deg), 0); 0s on isolated nodes
__device__ int    g_counts[MAX_N];       // degree histogram
__device__ int    g_offsets[MAX_N + 1];  // CSR row pointers (by dst)
__device__ int    g_pos[MAX_N];          // scatter cursors
__device__ int    g_src[MAX_E];          // CSR: source node per slot
__device__ int    g_blocksums[MAX_SCAN_BLOCKS];
__device__ int    g_blockoffs[MAX_SCAN_BLOCKS];

// ---------------------------------------------------------------------------
// 1) degree histogram — read only the first E/2 interactions, update both
//    endpoints (second half of edge_index is the exact mirror).
// ---------------------------------------------------------------------------
__global__ void zero_counts_kernel(int n) {
    int i = blockIdx.x * blockDim.x + threadIdx.x;
    if (i < n) g_counts[i] = 0;
}

__global__ void count_kernel(const int* __restrict__ edge, int E, int E2) {
    int e = blockIdx.x * blockDim.x + threadIdx.x;
    if (e < E2) {
        int u = edge[e];        // row of first half
        int i = edge[E + e];    // col of first half
        atomicAdd(&g_counts[i], 1);   // dst of (u,i)
        atomicAdd(&g_counts[u], 1);   // dst of mirrored (i,u)
    }
}

// ---------------------------------------------------------------------------
// 2) multi-block exclusive scan of counts -> offsets (3 phases)
//    Phase A also produces g_dinvs (fused — counts already streaming).
// ---------------------------------------------------------------------------
__global__ __launch_bounds__(SCAN_TB)
void scan_partial_kernel(int n) {
    __shared__ int warp_sums[SCAN_TB / 32];
    const int base = blockIdx.x * SCAN_CHUNK;
    const int t = threadIdx.x;

    int s = 0;
    #pragma unroll
    for (int i = 0; i < SCAN_ITEMS; i++) {
        int idx = base + i * SCAN_TB + t;       // coalesced
        if (idx < n) {
            int c = g_counts[idx];
            s += c;
            float d  = (c > 0) ? rsqrtf((float)c) : 0.0f;
            float sd = (c > 0) ? sqrtf((float)c)  : 0.0f;
            g_dinvs[idx] = make_float4(d, d * d, sd, 0.0f);
        }
    }
    #pragma unroll
    for (int o = 16; o > 0; o >>= 1) s += __shfl_down_sync(0xffffffffu, s, o);
    if ((t & 31) == 0) warp_sums[t >> 5] = s;
    __syncthreads();
    if (t < SCAN_TB / 32) {
        int v = warp_sums[t];
        #pragma unroll
        for (int o = SCAN_TB / 64; o > 0; o >>= 1) v += __shfl_down_sync(0xffffffffu, v, o);
        if (t == 0) g_blocksums[blockIdx.x] = v;
    }
}

__global__ __launch_bounds__(MAX_SCAN_BLOCKS)
void scan_blocksums_kernel(int nb, int n, int E) {
    __shared__ int sh[MAX_SCAN_BLOCKS];
    const int t = threadIdx.x;
    sh[t] = (t < nb) ? g_blocksums[t] : 0;
    __syncthreads();
    #pragma unroll
    for (int off = 1; off < MAX_SCAN_BLOCKS; off <<= 1) {
        int v = (t >= off) ? sh[t - off] : 0;
        __syncthreads();
        sh[t] += v;
        __syncthreads();
    }
    if (t < nb) g_blockoffs[t] = (t == 0) ? 0 : sh[t - 1];
    if (t == 0) g_offsets[n] = E;
}

__global__ __launch_bounds__(SCAN_TB)
void scan_write_kernel(int n) {
    __shared__ int thread_sums[SCAN_TB];
    const int base = blockIdx.x * SCAN_CHUNK;
    const int t = threadIdx.x;
    const int lo = base + t * SCAN_ITEMS;

    int c[SCAN_ITEMS];
    int s = 0;
    #pragma unroll
    for (int i = 0; i < SCAN_ITEMS; i++) {
        int idx = lo + i;
        c[i] = (idx < n) ? g_counts[idx] : 0;
        s += c[i];
    }
    thread_sums[t] = s;
    __syncthreads();
    #pragma unroll
    for (int off = 1; off < SCAN_TB; off <<= 1) {
        int v = (t >= off) ? thread_sums[t - off] : 0;
        __syncthreads();
        thread_sums[t] += v;
        __syncthreads();
    }
    int prefix = g_blockoffs[blockIdx.x] + ((t == 0) ? 0 : thread_sums[t - 1]);
    #pragma unroll
    for (int i = 0; i < SCAN_ITEMS; i++) {
        int idx = lo + i;
        if (idx < n) {
            g_offsets[idx] = prefix;
            g_pos[idx]     = prefix;
            prefix += c[i];
        }
    }
}

// ---------------------------------------------------------------------------
// 3) scatter — first half only; each interaction fills both endpoint lists
// ---------------------------------------------------------------------------
__global__ void fill_kernel(const int* __restrict__ edge, int E, int E2) {
    int e = blockIdx.x * blockDim.x + threadIdx.x;
    if (e >= E2) return;
    int u = edge[e];
    int i = edge[E + e];
    int s1 = atomicAdd(&g_pos[i], 1);
    g_src[s1] = u;
    int s2 = atomicAdd(&g_pos[u], 1);
    g_src[s2] = i;
}

// ---------------------------------------------------------------------------
// 4) init: A = w0 = dinv .* x0   (out deferred to last pull)
// ---------------------------------------------------------------------------
__global__ void init_kernel(const float* __restrict__ ue, const float* __restrict__ ie,
                            int nu_elems, int total) {
    int i = blockIdx.x * blockDim.x + threadIdx.x;
    if (i < total) {
        float v = (i < nu_elems) ? ue[i] : ie[i - nu_elems];
        g_bufA[i] = v * g_dinvs[i >> 6].x;
    }
}

// ---------------------------------------------------------------------------
// 5) pull pass: S[n] = sum_{k in csr(n)} W[src[k]]   (pure adds)
//    MID:  Y[n] = dinv^2 * S          (w_{l+1})
//    LAST: out[n] = 0.25*(x0 + sqrtdeg*(w1+w2) + dinv*S3)
//    16 threads (half-warp) per node, one float4 lane each; 4 gathers in
//    flight per thread.
// ---------------------------------------------------------------------------
template <bool A_TO_B, bool LAST>
__global__ __launch_bounds__(256)
void pull_kernel(int N, int nu_nodes,
                 const float* __restrict__ ue, const float* __restrict__ ie,
                 float* __restrict__ out) {
    int t = blockIdx.x * blockDim.x + threadIdx.x;
    int node = t >> 4;
    if (node >= N) return;
    int c = (t & 15) << 2;

    const float* __restrict__ X = A_TO_B ? g_bufA : g_bufB;
    float*       __restrict__ Y = A_TO_B ? g_bufB : g_bufA;

    const int beg = g_offsets[node];
    const int end = g_offsets[node + 1];

    float4 a0 = make_float4(0.f, 0.f, 0.f, 0.f);
    float4 a1 = make_float4(0.f, 0.f, 0.f, 0.f);
    float4 a2 = make_float4(0.f, 0.f, 0.f, 0.f);
    float4 a3 = make_float4(0.f, 0.f, 0.f, 0.f);

    int k = beg;
    for (; k + 3 < end; k += 4) {
        int s0 = g_src[k], s1 = g_src[k + 1], s2 = g_src[k + 2], s3 = g_src[k + 3];
        float4 v0 = *reinterpret_cast<const float4*>(X + (size_t)s0 * DIM + c);
        float4 v1 = *reinterpret_cast<const float4*>(X + (size_t)s1 * DIM + c);
        float4 v2 = *reinterpret_cast<const float4*>(X + (size_t)s2 * DIM + c);
        float4 v3 = *reinterpret_cast<const float4*>(X + (size_t)s3 * DIM + c);
        a0.x += v0.x; a0.y += v0.y; a0.z += v0.z; a0.w += v0.w;
        a1.x += v1.x; a1.y += v1.y; a1.z += v1.z; a1.w += v1.w;
        a2.x += v2.x; a2.y += v2.y; a2.z += v2.z; a2.w += v2.w;
        a3.x += v3.x; a3.y += v3.y; a3.z += v3.z; a3.w += v3.w;
    }
    for (; k < end; k++) {
        int s0 = g_src[k];
        float4 v0 = *reinterpret_cast<const float4*>(X + (size_t)s0 * DIM + c);
        a0.x += v0.x; a0.y += v0.y; a0.z += v0.z; a0.w += v0.w;
    }

    float sx = (a0.x + a1.x) + (a2.x + a3.x);
    float sy = (a0.y + a1.y) + (a2.y + a3.y);
    float sz = (a0.z + a1.z) + (a2.z + a3.z);
    float sw = (a0.w + a1.w) + (a2.w + a3.w);

    float4 dv = g_dinvs[node];          // (dinv, dinv^2, sqrtdeg, 0)

    if (!LAST) {
        float4 r;
        r.x = dv.y * sx; r.y = dv.y * sy; r.z = dv.y * sz; r.w = dv.y * sw;
        *reinterpret_cast<float4*>(Y + (size_t)node * DIM + c) = r;
    } else {
        // x0 row (from inputs), w1 (bufB), w2 (bufA == X here)
        const float* x0row = (node < nu_nodes)
            ? (ue + (size_t)node * DIM)
            : (ie + (size_t)(node - nu_nodes) * DIM);
        float4 x0 = *reinterpret_cast<const float4*>(x0row + c);
        float4 w1 = *reinterpret_cast<const float4*>(g_bufB + (size_t)node * DIM + c);
        float4 w2 = *reinterpret_cast<const float4*>(g_bufA + (size_t)node * DIM + c);

        float4 r;
        r.x = 0.25f * (x0.x + dv.z * (w1.x + w2.x) + dv.x * sx);
        r.y = 0.25f * (x0.y + dv.z * (w1.y + w2.y) + dv.x * sy);
        r.z = 0.25f * (x0.z + dv.z * (w1.z + w2.z) + dv.x * sz);
        r.w = 0.25f * (x0.w + dv.z * (w1.w + w2.w) + dv.x * sw);
        *reinterpret_cast<float4*>(out + (size_t)node * DIM + c) = r;
    }
}

// ---------------------------------------------------------------------------
// kernel_launch
// inputs: [0] user_emb f32 [100000*64], [1] item_emb f32 [50000*64],
//         [2] edge_index int32 [2 * 1200000]
// output: f32 [150000*64]
// ---------------------------------------------------------------------------
extern "C" void kernel_launch(void* const* d_in, const int* in_sizes, int n_in,
                              void* d_out, int out_size) {
    const float* user_emb = (const float*)d_in[0];
    const float* item_emb = (const float*)d_in[1];
    const int*   edge     = (const int*)d_in[2];
    float*       out      = (float*)d_out;

    const int nu_elems = in_sizes[0];
    const int ni_elems = in_sizes[1];
    const int E        = in_sizes[2] / 2;
    const int E2       = E / 2;                 // original interactions
    const int NU       = nu_elems / DIM;
    const int N        = NU + ni_elems / DIM;
    const int total    = N * DIM;

    const int TB = 256;
    const int nblk  = (N + TB - 1) / TB;
    const int hblk  = (E2 + TB - 1) / TB;
    const int tblk  = (total + TB - 1) / TB;
    const int pullb = (N * 16 + TB - 1) / TB;
    const int scanb = (N + SCAN_CHUNK - 1) / SCAN_CHUNK;

    // CSR build (by destination; mirrored half handled implicitly)
    zero_counts_kernel<<<nblk, TB>>>(N);
    count_kernel<<<hblk, TB>>>(edge, E, E2);
    scan_partial_kernel<<<scanb, SCAN_TB>>>(N);        // also fills g_dinvs
    scan_blocksums_kernel<<<1, MAX_SCAN_BLOCKS>>>(scanb, N, E);
    scan_write_kernel<<<scanb, SCAN_TB>>>(N);
    fill_kernel<<<hblk, TB>>>(edge, E, E2);

    // w0
    init_kernel<<<tblk, TB>>>(user_emb, item_emb, nu_elems, total);

    // 3 propagation layers; out materialized only in the last one
    pull_kernel<true , false><<<pullb, TB>>>(N, NU, user_emb, item_emb, out); // A->B (w1)
    pull_kernel<false, false><<<pullb, TB>>>(N, NU, user_emb, item_emb, out); // B->A (w2)
    pull_kernel<true , true ><<<pullb, TB>>>(N, NU, user_emb, item_emb, out); // A-> out
}

// round 7
// speedup vs baseline: 1.0443x; 1.0443x over previous
#include <cuda_runtime.h>
#include <stdint.h>

#define DIM   64
#define MAX_N 150016           // 100000 users + 50000 items, padded
#define MAX_E 1300000          // actual E = 1,200,000 (incl. flipped copy)

#define SCAN_TB    256
#define SCAN_ITEMS 8           // 2048 elements per block
#define SCAN_CHUNK (SCAN_TB * SCAN_ITEMS)
#define MAX_SCAN_BLOCKS 512

// ---------------------------------------------------------------------------
// Scratch: __device__ globals only (no allocations allowed anywhere).
// ---------------------------------------------------------------------------
__device__ float  g_bufA[MAX_N * DIM];   // ping (holds w = dinv .* x)
__device__ float  g_bufB[MAX_N * DIM];   // pong
__device__ float2 g_dinvs[MAX_N];        // (dinv, dinv^2); 0 on isolated nodes
__device__ int    g_counts[MAX_N];       // degree histogram
__device__ int    g_offsets[MAX_N + 1];  // CSR row pointers (by dst)
__device__ int    g_pos[MAX_N];          // scatter cursors
__device__ int    g_src[MAX_E];          // CSR: source node per slot
__device__ int    g_blocksums[MAX_SCAN_BLOCKS];
__device__ int    g_blockoffs[MAX_SCAN_BLOCKS];

// ---------------------------------------------------------------------------
// 1) degree histogram — read only the first E/2 interactions, update both
//    endpoints (second half of edge_index is the exact mirror).
// ---------------------------------------------------------------------------
__global__ void zero_counts_kernel(int n) {
    int i = blockIdx.x * blockDim.x + threadIdx.x;
    if (i < n) g_counts[i] = 0;
}

__global__ void count_kernel(const int* __restrict__ edge, int E, int E2) {
    int e = blockIdx.x * blockDim.x + threadIdx.x;
    if (e < E2) {
        int u = edge[e];        // row of first half
        int i = edge[E + e];    // col of first half
        atomicAdd(&g_counts[i], 1);   // dst of (u,i)
        atomicAdd(&g_counts[u], 1);   // dst of mirrored (i,u)
    }
}

// ---------------------------------------------------------------------------
// 2) multi-block exclusive scan of counts -> offsets (3 phases)
//    Phase A also produces g_dinvs (fused — counts already streaming).
// ---------------------------------------------------------------------------
__global__ __launch_bounds__(SCAN_TB)
void scan_partial_kernel(int n) {
    __shared__ int warp_sums[SCAN_TB / 32];
    const int base = blockIdx.x * SCAN_CHUNK;
    const int t = threadIdx.x;

    int s = 0;
    #pragma unroll
    for (int i = 0; i < SCAN_ITEMS; i++) {
        int idx = base + i * SCAN_TB + t;       // coalesced
        if (idx < n) {
            int c = g_counts[idx];
            s += c;
            float d = (c > 0) ? rsqrtf((float)c) : 0.0f;
            g_dinvs[idx] = make_float2(d, d * d);
        }
    }
    #pragma unroll
    for (int o = 16; o > 0; o >>= 1) s += __shfl_down_sync(0xffffffffu, s, o);
    if ((t & 31) == 0) warp_sums[t >> 5] = s;
    __syncthreads();
    if (t < SCAN_TB / 32) {
        int v = warp_sums[t];
        #pragma unroll
        for (int o = SCAN_TB / 64; o > 0; o >>= 1) v += __shfl_down_sync(0xffffffffu, v, o);
        if (t == 0) g_blocksums[blockIdx.x] = v;
    }
}

__global__ __launch_bounds__(MAX_SCAN_BLOCKS)
void scan_blocksums_kernel(int nb, int n, int E) {
    __shared__ int sh[MAX_SCAN_BLOCKS];
    const int t = threadIdx.x;
    sh[t] = (t < nb) ? g_blocksums[t] : 0;
    __syncthreads();
    #pragma unroll
    for (int off = 1; off < MAX_SCAN_BLOCKS; off <<= 1) {
        int v = (t >= off) ? sh[t - off] : 0;
        __syncthreads();
        sh[t] += v;
        __syncthreads();
    }
    if (t < nb) g_blockoffs[t] = (t == 0) ? 0 : sh[t - 1];
    if (t == 0) g_offsets[n] = E;
}

__global__ __launch_bounds__(SCAN_TB)
void scan_write_kernel(int n) {
    __shared__ int thread_sums[SCAN_TB];
    const int base = blockIdx.x * SCAN_CHUNK;
    const int t = threadIdx.x;
    const int lo = base + t * SCAN_ITEMS;

    int c[SCAN_ITEMS];
    int s = 0;
    #pragma unroll
    for (int i = 0; i < SCAN_ITEMS; i++) {
        int idx = lo + i;
        c[i] = (idx < n) ? g_counts[idx] : 0;
        s += c[i];
    }
    thread_sums[t] = s;
    __syncthreads();
    #pragma unroll
    for (int off = 1; off < SCAN_TB; off <<= 1) {
        int v = (t >= off) ? thread_sums[t - off] : 0;
        __syncthreads();
        thread_sums[t] += v;
        __syncthreads();
    }
    int prefix = g_blockoffs[blockIdx.x] + ((t == 0) ? 0 : thread_sums[t - 1]);
    #pragma unroll
    for (int i = 0; i < SCAN_ITEMS; i++) {
        int idx = lo + i;
        if (idx < n) {
            g_offsets[idx] = prefix;
            g_pos[idx]     = prefix;
            prefix += c[i];
        }
    }
}

// ---------------------------------------------------------------------------
// 3) scatter — first half only; each interaction fills both endpoint lists
// ---------------------------------------------------------------------------
__global__ void fill_kernel(const int* __restrict__ edge, int E, int E2) {
    int e = blockIdx.x * blockDim.x + threadIdx.x;
    if (e >= E2) return;
    int u = edge[e];
    int i = edge[E + e];
    int s1 = atomicAdd(&g_pos[i], 1);
    g_src[s1] = u;
    int s2 = atomicAdd(&g_pos[u], 1);
    g_src[s2] = i;
}

// ---------------------------------------------------------------------------
// 4) init: out = 0.25 * x0;  A = w0 = dinv .* x0
// ---------------------------------------------------------------------------
__global__ void init_kernel(const float* __restrict__ ue, const float* __restrict__ ie,
                            int nu_elems, int total, float* __restrict__ out) {
    int i = blockIdx.x * blockDim.x + threadIdx.x;
    if (i < total) {
        float v = (i < nu_elems) ? ue[i] : ie[i - nu_elems];
        out[i]    = 0.25f * v;
        g_bufA[i] = v * g_dinvs[i >> 6].x;
    }
}

// ---------------------------------------------------------------------------
// 5) pull pass: S[n] = sum_{k in csr(n)} W[src[k]]   (pure adds, no per-edge norm)
//    out[n] += 0.25 * dinv[n]   * S[n]
//    Y[n]   =        dinv[n]^2 * S[n]   (skipped on last layer)
//    16 threads (half-warp) per node, one float4 lane each; 2-edge unroll with
//    dual accumulators for 2 gathers in flight per thread.
// ---------------------------------------------------------------------------
template <bool A_TO_B, bool LAST>
__global__ __launch_bounds__(256)
void pull_kernel(int N, float* __restrict__ out) {
    int t = blockIdx.x * blockDim.x + threadIdx.x;
    int node = t >> 4;
    if (node >= N) return;
    int c = (t & 15) << 2;

    const float* __restrict__ X = A_TO_B ? g_bufA : g_bufB;
    float*       __restrict__ Y = A_TO_B ? g_bufB : g_bufA;

    const int beg = g_offsets[node];
    const int end = g_offsets[node + 1];

    float a0x = 0.f, a0y = 0.f, a0z = 0.f, a0w = 0.f;
    float a1x = 0.f, a1y = 0.f, a1z = 0.f, a1w = 0.f;

    int k = beg;
    for (; k + 1 < end; k += 2) {
        int s0 = g_src[k];
        int s1 = g_src[k + 1];
        float4 v0 = *reinterpret_cast<const float4*>(X + (size_t)s0 * DIM + c);
        float4 v1 = *reinterpret_cast<const float4*>(X + (size_t)s1 * DIM + c);
        a0x += v0.x; a0y += v0.y; a0z += v0.z; a0w += v0.w;
        a1x += v1.x; a1y += v1.y; a1z += v1.z; a1w += v1.w;
    }
    if (k < end) {
        int s0 = g_src[k];
        float4 v0 = *reinterpret_cast<const float4*>(X + (size_t)s0 * DIM + c);
        a0x += v0.x; a0y += v0.y; a0z += v0.z; a0w += v0.w;
    }

    float sx = a0x + a1x, sy = a0y + a1y, sz = a0z + a1z, sw = a0w + a1w;

    float2 dv = g_dinvs[node];          // (dinv, dinv^2); 0 on isolated nodes
    float e = 0.25f * dv.x;

    float4* op = reinterpret_cast<float4*>(out + (size_t)node * DIM + c);
    float4 ov = *op;
    ov.x = fmaf(e, sx, ov.x);
    ov.y = fmaf(e, sy, ov.y);
    ov.z = fmaf(e, sz, ov.z);
    ov.w = fmaf(e, sw, ov.w);
    *op = ov;

    if (!LAST) {
        float4 r;
        r.x = dv.y * sx; r.y = dv.y * sy; r.z = dv.y * sz; r.w = dv.y * sw;
        *reinterpret_cast<float4*>(Y + (size_t)node * DIM + c) = r;
    }
}

// ---------------------------------------------------------------------------
// kernel_launch
// inputs: [0] user_emb f32 [100000*64], [1] item_emb f32 [50000*64],
//         [2] edge_index int32 [2 * 1200000]
// output: f32 [150000*64]
// ---------------------------------------------------------------------------
extern "C" void kernel_launch(void* const* d_in, const int* in_sizes, int n_in,
                              void* d_out, int out_size) {
    const float* user_emb = (const float*)d_in[0];
    const float* item_emb = (const float*)d_in[1];
    const int*   edge     = (const int*)d_in[2];
    float*       out      = (float*)d_out;

    const int nu_elems = in_sizes[0];
    const int ni_elems = in_sizes[1];
    const int E        = in_sizes[2] / 2;
    const int E2       = E / 2;                 // original interactions
    const int N        = nu_elems / DIM + ni_elems / DIM;
    const int total    = N * DIM;

    const int TB = 256;
    const int nblk  = (N + TB - 1) / TB;
    const int hblk  = (E2 + TB - 1) / TB;
    const int tblk  = (total + TB - 1) / TB;
    const int pullb = (N * 16 + TB - 1) / TB;
    const int scanb = (N + SCAN_CHUNK - 1) / SCAN_CHUNK;

    // CSR build (by destination; mirrored half handled implicitly)
    zero_counts_kernel<<<nblk, TB>>>(N);
    count_kernel<<<hblk, TB>>>(edge, E, E2);
    scan_partial_kernel<<<scanb, SCAN_TB>>>(N);        // also fills g_dinvs
    scan_blocksums_kernel<<<1, MAX_SCAN_BLOCKS>>>(scanb, N, E);
    scan_write_kernel<<<scanb, SCAN_TB>>>(N);
    fill_kernel<<<hblk, TB>>>(edge, E, E2);

    // x0 / w0 and pooled output init
    init_kernel<<<tblk, TB>>>(user_emb, item_emb, nu_elems, total, out);

    // 3 propagation layers, out accumulation fused; last layer skips Y write
    pull_kernel<true , false><<<pullb, TB>>>(N, out);   // A -> B
    pull_kernel<false, false><<<pullb, TB>>>(N, out);   // B -> A
    pull_kernel<true , true ><<<pullb, TB>>>(N, out);   // A -> (discard)
}

// round 8
// speedup vs baseline: 1.2149x; 1.1634x over previous
#include <cuda_runtime.h>
#include <cuda_fp16.h>
#include <stdint.h>

#define DIM   64
#define MAX_N 150016           // 100000 users + 50000 items, padded
#define MAX_E 1300000          // actual E = 1,200,000 (incl. flipped copy)

#define SCAN_TB    256
#define SCAN_ITEMS 8           // 2048 elements per block
#define SCAN_CHUNK (SCAN_TB * SCAN_ITEMS)
#define MAX_SCAN_BLOCKS 512

// ---------------------------------------------------------------------------
// Scratch: __device__ globals only (no allocations allowed anywhere).
// Ping-pong buffers hold w = dinv .* x in fp16 (4 halves per uint2 lane-chunk;
// 16 lane-chunks per 64-dim node row = 128 B).
// ---------------------------------------------------------------------------
__device__ uint2  g_bufA[MAX_N * 16];    // ping (fp16 payload)
__device__ uint2  g_bufB[MAX_N * 16];    // pong (fp16 payload)
__device__ float2 g_dinvs[MAX_N];        // (dinv, dinv^2); 0 on isolated nodes
__device__ int    g_counts[MAX_N];       // degree histogram
__device__ int    g_offsets[MAX_N + 1];  // CSR row pointers (by dst)
__device__ int    g_pos[MAX_N];          // scatter cursors
__device__ int    g_src[MAX_E];          // CSR: source node per slot
__device__ int    g_blocksums[MAX_SCAN_BLOCKS];
__device__ int    g_blockoffs[MAX_SCAN_BLOCKS];

// ---------------------------------------------------------------------------
// 1) histogram of destinations (full edge list — R5 structure)
// ---------------------------------------------------------------------------
__global__ void zero_counts_kernel(int n) {
    int i = blockIdx.x * blockDim.x + threadIdx.x;
    if (i < n) g_counts[i] = 0;
}

__global__ void count_kernel(const int* __restrict__ edge, int E) {
    int e = blockIdx.x * blockDim.x + threadIdx.x;
    if (e < E) atomicAdd(&g_counts[edge[E + e]], 1);
}

// deg^{-1/2}, deg^{-1}; zeros on isolated nodes (never gathered).
__global__ void dinv_kernel(int n) {
    int i = blockIdx.x * blockDim.x + threadIdx.x;
    if (i < n) {
        int c = g_counts[i];
        float d = (c > 0) ? rsqrtf((float)c) : 0.0f;
        g_dinvs[i] = make_float2(d, d * d);
    }
}

// ---------------------------------------------------------------------------
// 2) multi-block exclusive scan of counts -> offsets (3 phases)
// ---------------------------------------------------------------------------
__global__ __launch_bounds__(SCAN_TB)
void scan_partial_kernel(int n) {
    __shared__ int warp_sums[SCAN_TB / 32];
    const int base = blockIdx.x * SCAN_CHUNK;
    const int t = threadIdx.x;

    int s = 0;
    #pragma unroll
    for (int i = 0; i < SCAN_ITEMS; i++) {
        int idx = base + i * SCAN_TB + t;       // coalesced
        if (idx < n) s += g_counts[idx];
    }
    #pragma unroll
    for (int o = 16; o > 0; o >>= 1) s += __shfl_down_sync(0xffffffffu, s, o);
    if ((t & 31) == 0) warp_sums[t >> 5] = s;
    __syncthreads();
    if (t < SCAN_TB / 32) {
        int v = warp_sums[t];
        #pragma unroll
        for (int o = SCAN_TB / 64; o > 0; o >>= 1) v += __shfl_down_sync(0xffffffffu, v, o);
        if (t == 0) g_blocksums[blockIdx.x] = v;
    }
}

__global__ __launch_bounds__(MAX_SCAN_BLOCKS)
void scan_blocksums_kernel(int nb, int n, int E) {
    __shared__ int sh[MAX_SCAN_BLOCKS];
    const int t = threadIdx.x;
    sh[t] = (t < nb) ? g_blocksums[t] : 0;
    __syncthreads();
    #pragma unroll
    for (int off = 1; off < MAX_SCAN_BLOCKS; off <<= 1) {
        int v = (t >= off) ? sh[t - off] : 0;
        __syncthreads();
        sh[t] += v;
        __syncthreads();
    }
    if (t < nb) g_blockoffs[t] = (t == 0) ? 0 : sh[t - 1];
    if (t == 0) g_offsets[n] = E;
}

__global__ __launch_bounds__(SCAN_TB)
void scan_write_kernel(int n) {
    __shared__ int thread_sums[SCAN_TB];
    const int base = blockIdx.x * SCAN_CHUNK;
    const int t = threadIdx.x;
    const int lo = base + t * SCAN_ITEMS;

    int c[SCAN_ITEMS];
    int s = 0;
    #pragma unroll
    for (int i = 0; i < SCAN_ITEMS; i++) {
        int idx = lo + i;
        c[i] = (idx < n) ? g_counts[idx] : 0;
        s += c[i];
    }
    thread_sums[t] = s;
    __syncthreads();
    #pragma unroll
    for (int off = 1; off < SCAN_TB; off <<= 1) {
        int v = (t >= off) ? thread_sums[t - off] : 0;
        __syncthreads();
        thread_sums[t] += v;
        __syncthreads();
    }
    int prefix = g_blockoffs[blockIdx.x] + ((t == 0) ? 0 : thread_sums[t - 1]);
    #pragma unroll
    for (int i = 0; i < SCAN_ITEMS; i++) {
        int idx = lo + i;
        if (idx < n) {
            g_offsets[idx] = prefix;
            g_pos[idx]     = prefix;
            prefix += c[i];
        }
    }
}

// ---------------------------------------------------------------------------
// 3) scatter edges into CSR slots (full edge list — R5 structure)
// ---------------------------------------------------------------------------
__global__ void fill_kernel(const int* __restrict__ edge, int E) {
    int e = blockIdx.x * blockDim.x + threadIdx.x;
    if (e >= E) return;
    int r = edge[e];
    int c = edge[E + e];
    int slot = atomicAdd(&g_pos[c], 1);
    g_src[slot] = r;
}

// ---------------------------------------------------------------------------
// 4) init: out = 0.25 * x0;  A = w0 = fp16(dinv .* x0)
// ---------------------------------------------------------------------------
__global__ void init_kernel(const float* __restrict__ ue, const float* __restrict__ ie,
                            int nu_elems, int total, float* __restrict__ out) {
    int i = blockIdx.x * blockDim.x + threadIdx.x;
    if (i < total) {
        float v = (i < nu_elems) ? ue[i] : ie[i - nu_elems];
        out[i] = 0.25f * v;
        reinterpret_cast<__half*>(g_bufA)[i] = __float2half_rn(v * g_dinvs[i >> 6].x);
    }
}

// ---------------------------------------------------------------------------
// 5) pull pass: S[n] = sum_{k in csr(n)} W[src[k]]  (fp16 payload, fp32 accum)
//    out[n] += 0.25 * dinv[n]   * S[n]
//    Y[n]   = fp16( dinv[n]^2 * S[n] )   (skipped on last layer)
//    16 threads (half-warp) per node, one uint2 (4 halves) lane each;
//    2-edge unroll with dual accumulators -> 2 gathers in flight per thread.
// ---------------------------------------------------------------------------
__device__ __forceinline__ void acc_u2(const uint2 u, float& x, float& y, float& z, float& w) {
    float2 f0 = __half22float2(*reinterpret_cast<const __half2*>(&u.x));
    float2 f1 = __half22float2(*reinterpret_cast<const __half2*>(&u.y));
    x += f0.x; y += f0.y; z += f1.x; w += f1.y;
}

template <bool A_TO_B, bool LAST>
__global__ __launch_bounds__(256)
void pull_kernel(int N, float* __restrict__ out) {
    int t = blockIdx.x * blockDim.x + threadIdx.x;
    int node = t >> 4;
    if (node >= N) return;
    int lane = t & 15;

    const uint2* __restrict__ X = A_TO_B ? g_bufA : g_bufB;
    uint2*       __restrict__ Y = A_TO_B ? g_bufB : g_bufA;

    const int beg = g_offsets[node];
    const int end = g_offsets[node + 1];

    float a0x = 0.f, a0y = 0.f, a0z = 0.f, a0w = 0.f;
    float a1x = 0.f, a1y = 0.f, a1z = 0.f, a1w = 0.f;

    int k = beg;
    for (; k + 1 < end; k += 2) {
        int s0 = g_src[k];
        int s1 = g_src[k + 1];
        uint2 u0 = X[(size_t)s0 * 16 + lane];
        uint2 u1 = X[(size_t)s1 * 16 + lane];
        acc_u2(u0, a0x, a0y, a0z, a0w);
        acc_u2(u1, a1x, a1y, a1z, a1w);
    }
    if (k < end) {
        int s0 = g_src[k];
        uint2 u0 = X[(size_t)s0 * 16 + lane];
        acc_u2(u0, a0x, a0y, a0z, a0w);
    }

    float sx = a0x + a1x, sy = a0y + a1y, sz = a0z + a1z, sw = a0w + a1w;

    float2 dv = g_dinvs[node];          // (dinv, dinv^2); 0 on isolated nodes
    float e = 0.25f * dv.x;

    float4* op = reinterpret_cast<float4*>(out + (size_t)node * DIM + (lane << 2));
    float4 ov = *op;
    ov.x = fmaf(e, sx, ov.x);
    ov.y = fmaf(e, sy, ov.y);
    ov.z = fmaf(e, sz, ov.z);
    ov.w = fmaf(e, sw, ov.w);
    *op = ov;

    if (!LAST) {
        __half2 p0 = __floats2half2_rn(dv.y * sx, dv.y * sy);
        __half2 p1 = __floats2half2_rn(dv.y * sz, dv.y * sw);
        uint2 st;
        st.x = *reinterpret_cast<unsigned int*>(&p0);
        st.y = *reinterpret_cast<unsigned int*>(&p1);
        Y[(size_t)node * 16 + lane] = st;
    }
}

// ---------------------------------------------------------------------------
// kernel_launch
// inputs: [0] user_emb f32 [100000*64], [1] item_emb f32 [50000*64],
//         [2] edge_index int32 [2 * 1200000]
// output: f32 [150000*64]
// ---------------------------------------------------------------------------
extern "C" void kernel_launch(void* const* d_in, const int* in_sizes, int n_in,
                              void* d_out, int out_size) {
    const float* user_emb = (const float*)d_in[0];
    const float* item_emb = (const float*)d_in[1];
    const int*   edge     = (const int*)d_in[2];
    float*       out      = (float*)d_out;

    const int nu_elems = in_sizes[0];
    const int ni_elems = in_sizes[1];
    const int E        = in_sizes[2] / 2;
    const int N        = nu_elems / DIM + ni_elems / DIM;
    const int total    = N * DIM;

    const int TB = 256;
    const int nblk  = (N + TB - 1) / TB;
    const int eblk  = (E + TB - 1) / TB;
    const int tblk  = (total + TB - 1) / TB;
    const int pullb = (N * 16 + TB - 1) / TB;
    const int scanb = (N + SCAN_CHUNK - 1) / SCAN_CHUNK;

    // CSR build (by destination) — R5 structure
    zero_counts_kernel<<<nblk, TB>>>(N);
    count_kernel<<<eblk, TB>>>(edge, E);
    dinv_kernel<<<nblk, TB>>>(N);
    scan_partial_kernel<<<scanb, SCAN_TB>>>(N);
    scan_blocksums_kernel<<<1, MAX_SCAN_BLOCKS>>>(scanb, N, E);
    scan_write_kernel<<<scanb, SCAN_TB>>>(N);
    fill_kernel<<<eblk, TB>>>(edge, E);

    // x0 / w0 and pooled output init
    init_kernel<<<tblk, TB>>>(user_emb, item_emb, nu_elems, total, out);

    // 3 propagation layers, out accumulation fused; last layer skips Y write
    pull_kernel<true , false><<<pullb, TB>>>(N, out);   // A -> B
    pull_kernel<false, false><<<pullb, TB>>>(N, out);   // B -> A
    pull_kernel<true , true ><<<pullb, TB>>>(N, out);   // A -> (discard)
}

// round 9
// speedup vs baseline: 1.3254x; 1.0909x over previous
#include <cuda_runtime.h>
#include <cuda_fp16.h>
#include <stdint.h>

#define DIM   64
#define MAX_N 150016           // 100000 users + 50000 items, padded
#define MAX_E 1300000          // actual E = 1,200,000 (incl. flipped copy)

#define SCAN_TB    256
#define SCAN_ITEMS 8           // 2048 elements per block
#define SCAN_CHUNK (SCAN_TB * SCAN_ITEMS)
#define MAX_SCAN_BLOCKS 512

// ---------------------------------------------------------------------------
// Scratch: __device__ globals only (no allocations allowed anywhere).
// Ping-pong buffers hold w = dinv .* x in fp16 (4 halves per uint2 lane-chunk;
// 16 lane-chunks per 64-dim node row = 128 B).
// ---------------------------------------------------------------------------
__device__ uint2  g_bufA[MAX_N * 16];    // ping (w0, then w2)
__device__ uint2  g_bufB[MAX_N * 16];    // pong (w1)
__device__ float4 g_dinvs[MAX_N];        // (dinv, dinv^2, sqrt(deg), 0); 0s if isolated
__device__ int    g_counts[MAX_N];       // degree histogram
__device__ int    g_offsets[MAX_N + 1];  // CSR row pointers (by dst)
__device__ int    g_pos[MAX_N];          // scatter cursors
__device__ int    g_src[MAX_E];          // CSR: source node per slot
__device__ int    g_blocksums[MAX_SCAN_BLOCKS];
__device__ int    g_blockoffs[MAX_SCAN_BLOCKS];

// ---------------------------------------------------------------------------
// 1) histogram of destinations (full edge list — R5/R8 structure)
// ---------------------------------------------------------------------------
__global__ void zero_counts_kernel(int n) {
    int i = blockIdx.x * blockDim.x + threadIdx.x;
    if (i < n) g_counts[i] = 0;
}

__global__ void count_kernel(const int* __restrict__ edge, int E) {
    int e = blockIdx.x * blockDim.x + threadIdx.x;
    if (e < E) atomicAdd(&g_counts[edge[E + e]], 1);
}

// deg^{-1/2}, deg^{-1}, deg^{1/2}; zeros on isolated nodes (never gathered).
__global__ void dinv_kernel(int n) {
    int i = blockIdx.x * blockDim.x + threadIdx.x;
    if (i < n) {
        int c = g_counts[i];
        float d  = (c > 0) ? rsqrtf((float)c) : 0.0f;
        float sd = (c > 0) ? sqrtf((float)c)  : 0.0f;
        g_dinvs[i] = make_float4(d, d * d, sd, 0.0f);
    }
}

// ---------------------------------------------------------------------------
// 2) multi-block exclusive scan of counts -> offsets (3 phases)
// ---------------------------------------------------------------------------
__global__ __launch_bounds__(SCAN_TB)
void scan_partial_kernel(int n) {
    __shared__ int warp_sums[SCAN_TB / 32];
    const int base = blockIdx.x * SCAN_CHUNK;
    const int t = threadIdx.x;

    int s = 0;
    #pragma unroll
    for (int i = 0; i < SCAN_ITEMS; i++) {
        int idx = base + i * SCAN_TB + t;       // coalesced
        if (idx < n) s += g_counts[idx];
    }
    #pragma unroll
    for (int o = 16; o > 0; o >>= 1) s += __shfl_down_sync(0xffffffffu, s, o);
    if ((t & 31) == 0) warp_sums[t >> 5] = s;
    __syncthreads();
    if (t < SCAN_TB / 32) {
        int v = warp_sums[t];
        #pragma unroll
        for (int o = SCAN_TB / 64; o > 0; o >>= 1) v += __shfl_down_sync(0xffffffffu, v, o);
        if (t == 0) g_blocksums[blockIdx.x] = v;
    }
}

__global__ __launch_bounds__(MAX_SCAN_BLOCKS)
void scan_blocksums_kernel(int nb, int n, int E) {
    __shared__ int sh[MAX_SCAN_BLOCKS];
    const int t = threadIdx.x;
    sh[t] = (t < nb) ? g_blocksums[t] : 0;
    __syncthreads();
    #pragma unroll
    for (int off = 1; off < MAX_SCAN_BLOCKS; off <<= 1) {
        int v = (t >= off) ? sh[t - off] : 0;
        __syncthreads();
        sh[t] += v;
        __syncthreads();
    }
    if (t < nb) g_blockoffs[t] = (t == 0) ? 0 : sh[t - 1];
    if (t == 0) g_offsets[n] = E;
}

__global__ __launch_bounds__(SCAN_TB)
void scan_write_kernel(int n) {
    __shared__ int thread_sums[SCAN_TB];
    const int base = blockIdx.x * SCAN_CHUNK;
    const int t = threadIdx.x;
    const int lo = base + t * SCAN_ITEMS;

    int c[SCAN_ITEMS];
    int s = 0;
    #pragma unroll
    for (int i = 0; i < SCAN_ITEMS; i++) {
        int idx = lo + i;
        c[i] = (idx < n) ? g_counts[idx] : 0;
        s += c[i];
    }
    thread_sums[t] = s;
    __syncthreads();
    #pragma unroll
    for (int off = 1; off < SCAN_TB; off <<= 1) {
        int v = (t >= off) ? thread_sums[t - off] : 0;
        __syncthreads();
        thread_sums[t] += v;
        __syncthreads();
    }
    int prefix = g_blockoffs[blockIdx.x] + ((t == 0) ? 0 : thread_sums[t - 1]);
    #pragma unroll
    for (int i = 0; i < SCAN_ITEMS; i++) {
        int idx = lo + i;
        if (idx < n) {
            g_offsets[idx] = prefix;
            g_pos[idx]     = prefix;
            prefix += c[i];
        }
    }
}

// ---------------------------------------------------------------------------
// 3) scatter edges into CSR slots (full edge list)
// ---------------------------------------------------------------------------
__global__ void fill_kernel(const int* __restrict__ edge, int E) {
    int e = blockIdx.x * blockDim.x + threadIdx.x;
    if (e >= E) return;
    int r = edge[e];
    int c = edge[E + e];
    int slot = atomicAdd(&g_pos[c], 1);
    g_src[slot] = r;
}

// ---------------------------------------------------------------------------
// 4) init: A = w0 = fp16(dinv .* x0)   (out deferred to last pull)
// ---------------------------------------------------------------------------
__global__ void init_kernel(const float* __restrict__ ue, const float* __restrict__ ie,
                            int nu_elems, int total) {
    int i = blockIdx.x * blockDim.x + threadIdx.x;
    if (i < total) {
        float v = (i < nu_elems) ? ue[i] : ie[i - nu_elems];
        reinterpret_cast<__half*>(g_bufA)[i] = __float2half_rn(v * g_dinvs[i >> 6].x);
    }
}

// ---------------------------------------------------------------------------
// 5) pull pass: S[n] = sum_{k in csr(n)} W[src[k]]  (fp16 payload, fp32 accum)
//    MID:  Y[n] = fp16( dinv^2 * S )
//    LAST: out[n] = 0.25*( x0 + sqrtdeg*(w1+w2) + dinv*S )
//    16 threads (half-warp) per node, one uint2 (4 halves) lane each;
//    2-edge unroll with dual accumulators (proven R5/R8 loop).
// ---------------------------------------------------------------------------
__device__ __forceinline__ void acc_u2(const uint2 u, float& x, float& y, float& z, float& w) {
    float2 f0 = __half22float2(*reinterpret_cast<const __half2*>(&u.x));
    float2 f1 = __half22float2(*reinterpret_cast<const __half2*>(&u.y));
    x += f0.x; y += f0.y; z += f1.x; w += f1.y;
}

template <bool A_TO_B, bool LAST>
__global__ __launch_bounds__(256)
void pull_kernel(int N, int nu_nodes,
                 const float* __restrict__ ue, const float* __restrict__ ie,
                 float* __restrict__ out) {
    int t = blockIdx.x * blockDim.x + threadIdx.x;
    int node = t >> 4;
    if (node >= N) return;
    int lane = t & 15;

    const uint2* __restrict__ X = A_TO_B ? g_bufA : g_bufB;
    uint2*       __restrict__ Y = A_TO_B ? g_bufB : g_bufA;

    const int beg = g_offsets[node];
    const int end = g_offsets[node + 1];

    float a0x = 0.f, a0y = 0.f, a0z = 0.f, a0w = 0.f;
    float a1x = 0.f, a1y = 0.f, a1z = 0.f, a1w = 0.f;

    int k = beg;
    for (; k + 1 < end; k += 2) {
        int s0 = g_src[k];
        int s1 = g_src[k + 1];
        uint2 u0 = X[(size_t)s0 * 16 + lane];
        uint2 u1 = X[(size_t)s1 * 16 + lane];
        acc_u2(u0, a0x, a0y, a0z, a0w);
        acc_u2(u1, a1x, a1y, a1z, a1w);
    }
    if (k < end) {
        int s0 = g_src[k];
        uint2 u0 = X[(size_t)s0 * 16 + lane];
        acc_u2(u0, a0x, a0y, a0z, a0w);
    }

    float sx = a0x + a1x, sy = a0y + a1y, sz = a0z + a1z, sw = a0w + a1w;

    float4 dv = g_dinvs[node];          // (dinv, dinv^2, sqrtdeg, 0)

    if (!LAST) {
        __half2 p0 = __floats2half2_rn(dv.y * sx, dv.y * sy);
        __half2 p1 = __floats2half2_rn(dv.y * sz, dv.y * sw);
        uint2 st;
        st.x = *reinterpret_cast<unsigned int*>(&p0);
        st.y = *reinterpret_cast<unsigned int*>(&p1);
        Y[(size_t)node * 16 + lane] = st;
    } else {
        // x0 from inputs; w1 in bufB, w2 in bufA (== X for this launch)
        const float* x0row = (node < nu_nodes)
            ? (ue + (size_t)node * DIM)
            : (ie + (size_t)(node - nu_nodes) * DIM);
        float4 x0 = *reinterpret_cast<const float4*>(x0row + (lane << 2));

        uint2 u1 = g_bufB[(size_t)node * 16 + lane];
        uint2 u2 = g_bufA[(size_t)node * 16 + lane];
        float w1x = 0.f, w1y = 0.f, w1z = 0.f, w1w = 0.f;
        float w2x = 0.f, w2y = 0.f, w2z = 0.f, w2w = 0.f;
        acc_u2(u1, w1x, w1y, w1z, w1w);
        acc_u2(u2, w2x, w2y, w2z, w2w);

        float4 r;
        r.x = 0.25f * (x0.x + dv.z * (w1x + w2x) + dv.x * sx);
        r.y = 0.25f * (x0.y + dv.z * (w1y + w2y) + dv.x * sy);
        r.z = 0.25f * (x0.z + dv.z * (w1z + w2z) + dv.x * sz);
        r.w = 0.25f * (x0.w + dv.z * (w1w + w2w) + dv.x * sw);
        *reinterpret_cast<float4*>(out + (size_t)node * DIM + (lane << 2)) = r;
    }
}

// ---------------------------------------------------------------------------
// kernel_launch
// inputs: [0] user_emb f32 [100000*64], [1] item_emb f32 [50000*64],
//         [2] edge_index int32 [2 * 1200000]
// output: f32 [150000*64]
// ---------------------------------------------------------------------------
extern "C" void kernel_launch(void* const* d_in, const int* in_sizes, int n_in,
                              void* d_out, int out_size) {
    const float* user_emb = (const float*)d_in[0];
    const float* item_emb = (const float*)d_in[1];
    const int*   edge     = (const int*)d_in[2];
    float*       out      = (float*)d_out;

    const int nu_elems = in_sizes[0];
    const int ni_elems = in_sizes[1];
    const int E        = in_sizes[2] / 2;
    const int NU       = nu_elems / DIM;
    const int N        = NU + ni_elems / DIM;
    const int total    = N * DIM;

    const int TB = 256;
    const int nblk  = (N + TB - 1) / TB;
    const int eblk  = (E + TB - 1) / TB;
    const int tblk  = (total + TB - 1) / TB;
    const int pullb = (N * 16 + TB - 1) / TB;
    const int scanb = (N + SCAN_CHUNK - 1) / SCAN_CHUNK;

    // CSR build (by destination)
    zero_counts_kernel<<<nblk, TB>>>(N);
    count_kernel<<<eblk, TB>>>(edge, E);
    dinv_kernel<<<nblk, TB>>>(N);
    scan_partial_kernel<<<scanb, SCAN_TB>>>(N);
    scan_blocksums_kernel<<<1, MAX_SCAN_BLOCKS>>>(scanb, N, E);
    scan_write_kernel<<<scanb, SCAN_TB>>>(N);
    fill_kernel<<<eblk, TB>>>(edge, E);

    // w0 only (out deferred)
    init_kernel<<<tblk, TB>>>(user_emb, item_emb, nu_elems, total);

    // 3 propagation layers; out materialized only in the last one
    pull_kernel<true , false><<<pullb, TB>>>(N, NU, user_emb, item_emb, out); // A->B (w1)
    pull_kernel<false, false><<<pullb, TB>>>(N, NU, user_emb, item_emb, out); // B->A (w2)
    pull_kernel<true , true ><<<pullb, TB>>>(N, NU, user_emb, item_emb, out); // A-> out
}